// round 3
// baseline (speedup 1.0000x reference)
#include <cuda_runtime.h>
#include <math.h>

#define Bc 4
#define Pc 12
#define Qc 12
#define Nc 2048
#define Dc 32
#define DAYSc 7
#define PBDc (Pc*Bc*Dc)   // 1536
#define BDc (Bc*Dc)       // 128
#define EMAX 128

// ---------------- scratch (device globals; no allocation) ----------------
__device__ float g_ellv[Nc*EMAX];
__device__ int   g_elli[Nc*EMAX];
__device__ int   g_ellc[Nc];
__device__ float g_se[Nc*Dc];
__device__ float g_te[Bc*(Pc+Qc)*Dc];
__device__ float g_X0[Nc*PBDc];
__device__ float g_X1[Nc*PBDc];
__device__ float g_X2[Nc*PBDc];
__device__ float g_X3[Nc*PBDc];
__device__ float g_gpre[Pc*Bc*Nc*64];
__device__ float g_cpre[Pc*Bc*Nc*Dc];
__device__ float g_h [Nc*BDc];
__device__ float g_y1[Nc*BDc];
__device__ float g_y2[Nc*BDc];
__device__ float g_y3[Nc*BDc];
__device__ float g_rh[Nc*BDc];
__device__ float g_u [Nc*BDc];
__device__ float g_Wgx[128*64];
__device__ float g_Wgh[128*64];
__device__ float g_Wcx[128*32];
__device__ float g_Wch[128*32];

__device__ __forceinline__ float* buf_ptr(int s){
    switch(s){
        case 0: return g_X0; case 1: return g_X1; case 2: return g_X2; case 3: return g_X3;
        case 4: return g_h;  case 5: return g_y1; case 6: return g_y2; case 7: return g_y3;
        case 8: return g_rh;
    }
    return 0;
}

// ---------------- build ELL from dense L ----------------
__global__ void k_ell(const float* __restrict__ L){
    int row  = blockIdx.x*8 + (threadIdx.x>>5);
    int lane = threadIdx.x & 31;
    int cnt = 0;
    for(int c0=0;c0<Nc;c0+=32){
        float v = L[row*Nc + c0 + lane];
        unsigned m = __ballot_sync(0xffffffffu, v != 0.f);
        if(v != 0.f){
            int r = cnt + __popc(m & ((1u<<lane)-1u));
            if(r < EMAX){ g_elli[row*EMAX+r] = c0+lane; g_ellv[row*EMAX+r] = v; }
        }
        cnt += __popc(m);
    }
    if(lane==0) g_ellc[row] = cnt < EMAX ? cnt : EMAX;
}

// ---------------- pack gate/cand weights into (k*32+d)-major blocks ----------------
__global__ void k_pack(const float* __restrict__ Wg, const float* __restrict__ Wc){
    int i = blockIdx.x*blockDim.x + threadIdx.x;
    if(i < 128*64){
        int kd = i>>6, o = i&63; int k = kd>>5, d = kd&31;
        g_Wgx[i] = Wg[(k*64 + d)*64 + o];
        g_Wgh[i] = Wg[(k*64 + 32 + d)*64 + o];
    }
    if(i < 128*32){
        int kd = i>>5, o = i&31; int k = kd>>5, d = kd&31;
        g_Wcx[i] = Wc[(k*64 + d)*32 + o];
        g_Wch[i] = Wc[(k*64 + 32 + d)*32 + o];
    }
}

// ---------------- spatial embedding: se = relu(SE@W1+b1)@W2+b2 ----------------
__global__ void k_se(const float* __restrict__ SE, const float* __restrict__ W1,
                     const float* __restrict__ b1, const float* __restrict__ W2,
                     const float* __restrict__ b2){
    int n = blockIdx.x*8 + (threadIdx.x>>5);
    int lane = threadIdx.x & 31;
    float sein = SE[n*Dc + lane];
    float hid = b1[lane];
    #pragma unroll
    for(int d=0;d<32;d++) hid = fmaf(__shfl_sync(0xffffffffu, sein, d), W1[d*32+lane], hid);
    hid = fmaxf(hid, 0.f);
    float o = b2[lane];
    #pragma unroll
    for(int j=0;j<32;j++) o = fmaf(__shfl_sync(0xffffffffu, hid, j), W2[j*32+lane], o);
    g_se[n*Dc + lane] = o;
}

// ---------------- temporal embedding ----------------
__global__ void k_te(const int* __restrict__ TE, const float* __restrict__ W1,
                     const float* __restrict__ b1, const float* __restrict__ W2,
                     const float* __restrict__ b2){
    int bt = blockIdx.x;
    int lane = threadIdx.x;
    int day = TE[bt*2+0], tod = TE[bt*2+1];
    float hid = fmaxf(W1[day*32 + lane] + W1[(DAYSc+tod)*32 + lane] + b1[lane], 0.f);
    float o = b2[lane];
    #pragma unroll
    for(int j=0;j<32;j++) o = fmaf(__shfl_sync(0xffffffffu, hid, j), W2[j*32+lane], o);
    g_te[bt*32 + lane] = o;
}

// ---------------- input embedding + STE -> X0[n][(t*B+b)*32+d] ----------------
__global__ void k_xembed(const float* __restrict__ X, const float* __restrict__ W1,
                         const float* __restrict__ b1, const float* __restrict__ W2,
                         const float* __restrict__ b2){
    int r = blockIdx.x*8 + (threadIdx.x>>5);      // r = tb*N + n
    int lane = threadIdx.x & 31;
    int tb = r >> 11, n = r & 2047;
    int t = tb / Bc, b = tb % Bc;
    float xv = X[(b*Pc + t)*Nc + n];
    float h1 = fmaxf(fmaf(xv, W1[lane], b1[lane]), 0.f);
    float o = b2[lane] + g_se[n*32 + lane] + g_te[(b*(Pc+Qc) + t)*32 + lane];
    #pragma unroll
    for(int j=0;j<32;j++) o = fmaf(__shfl_sync(0xffffffffu, h1, j), W2[j*32+lane], o);
    g_X0[n*PBDc + tb*32 + lane] = o;
}

// ---------------- generic ELL SpMM: out = alpha*(L@in) - sub ----------------
__global__ void k_spmm(int si_, int ss_, int so_, int ncols, float alpha){
    const float* __restrict__ in  = buf_ptr(si_);
    const float* __restrict__ sub = (ss_ >= 0) ? buf_ptr(ss_) : 0;
    float* __restrict__ outp = buf_ptr(so_);
    int n = blockIdx.x;
    __shared__ float sv[EMAX];
    __shared__ int   sidx[EMAX];
    int cnt = g_ellc[n];
    for(int e=threadIdx.x; e<cnt; e+=blockDim.x){
        sv[e]   = g_ellv[n*EMAX + e];
        sidx[e] = g_elli[n*EMAX + e];
    }
    __syncthreads();
    for(int c=threadIdx.x; c<ncols; c+=blockDim.x){
        float a0=0.f, a1=0.f;
        int e=0;
        for(; e+1<cnt; e+=2){
            a0 = fmaf(sv[e],   in[sidx[e]*ncols + c],   a0);
            a1 = fmaf(sv[e+1], in[sidx[e+1]*ncols + c], a1);
        }
        if(e<cnt) a0 = fmaf(sv[e], in[sidx[e]*ncols + c], a0);
        float r = alpha*(a0+a1);
        if(sub) r -= sub[n*ncols + c];
        outp[n*ncols + c] = r;
    }
}

// ---------------- precompute gate_pre = sum_k Tk(x) @ Wgx_k + b_gate ----------------
__global__ __launch_bounds__(256) void k_pre_gate(const float* __restrict__ bg){
    int tb = blockIdx.y;
    int n0 = blockIdx.x*64;
    __shared__ float Ws[128*64];
    __shared__ float As[32*65];
    int tid = threadIdx.x;
    for(int i=tid;i<128*64;i+=256) Ws[i] = g_Wgx[i];
    int trow = tid>>4, tcol = tid&15;
    float acc[4][4];
    #pragma unroll
    for(int j=0;j<4;j++){ float bv = bg[tcol*4+j];
        #pragma unroll
        for(int i=0;i<4;i++) acc[i][j] = bv; }
    #pragma unroll
    for(int kk=0; kk<4; kk++){
        const float* __restrict__ Xa = buf_ptr(kk);
        __syncthreads();
        for(int i=tid; i<64*32; i+=256){
            int row = i>>5, k = i&31;
            As[k*65 + row] = Xa[(n0+row)*PBDc + tb*Dc + k];
        }
        __syncthreads();
        #pragma unroll
        for(int k=0;k<32;k++){
            float a0 = As[k*65 + trow*4 + 0];
            float a1 = As[k*65 + trow*4 + 1];
            float a2 = As[k*65 + trow*4 + 2];
            float a3 = As[k*65 + trow*4 + 3];
            float4 bv = *(const float4*)&Ws[(kk*32+k)*64 + tcol*4];
            acc[0][0]=fmaf(a0,bv.x,acc[0][0]); acc[0][1]=fmaf(a0,bv.y,acc[0][1]);
            acc[0][2]=fmaf(a0,bv.z,acc[0][2]); acc[0][3]=fmaf(a0,bv.w,acc[0][3]);
            acc[1][0]=fmaf(a1,bv.x,acc[1][0]); acc[1][1]=fmaf(a1,bv.y,acc[1][1]);
            acc[1][2]=fmaf(a1,bv.z,acc[1][2]); acc[1][3]=fmaf(a1,bv.w,acc[1][3]);
            acc[2][0]=fmaf(a2,bv.x,acc[2][0]); acc[2][1]=fmaf(a2,bv.y,acc[2][1]);
            acc[2][2]=fmaf(a2,bv.z,acc[2][2]); acc[2][3]=fmaf(a2,bv.w,acc[2][3]);
            acc[3][0]=fmaf(a3,bv.x,acc[3][0]); acc[3][1]=fmaf(a3,bv.y,acc[3][1]);
            acc[3][2]=fmaf(a3,bv.z,acc[3][2]); acc[3][3]=fmaf(a3,bv.w,acc[3][3]);
        }
    }
    #pragma unroll
    for(int i=0;i<4;i++){
        int n = n0 + trow*4 + i;
        #pragma unroll
        for(int j=0;j<4;j++)
            g_gpre[(tb*Nc + n)*64 + tcol*4 + j] = acc[i][j];
    }
}

// ---------------- precompute cand_pre ----------------
__global__ __launch_bounds__(256) void k_pre_cand(const float* __restrict__ bc){
    int tb = blockIdx.y;
    int n0 = blockIdx.x*64;
    __shared__ float Ws[128*32];
    __shared__ float As[32*65];
    int tid = threadIdx.x;
    for(int i=tid;i<128*32;i+=256) Ws[i] = g_Wcx[i];
    int trow = tid>>4, tcol = tid&15;
    float acc[4][2];
    #pragma unroll
    for(int j=0;j<2;j++){ float bv = bc[tcol*2+j];
        #pragma unroll
        for(int i=0;i<4;i++) acc[i][j] = bv; }
    #pragma unroll
    for(int kk=0; kk<4; kk++){
        const float* __restrict__ Xa = buf_ptr(kk);
        __syncthreads();
        for(int i=tid; i<64*32; i+=256){
            int row = i>>5, k = i&31;
            As[k*65 + row] = Xa[(n0+row)*PBDc + tb*Dc + k];
        }
        __syncthreads();
        #pragma unroll
        for(int k=0;k<32;k++){
            float a0 = As[k*65 + trow*4 + 0];
            float a1 = As[k*65 + trow*4 + 1];
            float a2 = As[k*65 + trow*4 + 2];
            float a3 = As[k*65 + trow*4 + 3];
            float b0 = Ws[(kk*32+k)*32 + tcol*2 + 0];
            float b1 = Ws[(kk*32+k)*32 + tcol*2 + 1];
            acc[0][0]=fmaf(a0,b0,acc[0][0]); acc[0][1]=fmaf(a0,b1,acc[0][1]);
            acc[1][0]=fmaf(a1,b0,acc[1][0]); acc[1][1]=fmaf(a1,b1,acc[1][1]);
            acc[2][0]=fmaf(a2,b0,acc[2][0]); acc[2][1]=fmaf(a2,b1,acc[2][1]);
            acc[3][0]=fmaf(a3,b0,acc[3][0]); acc[3][1]=fmaf(a3,b1,acc[3][1]);
        }
    }
    #pragma unroll
    for(int i=0;i<4;i++){
        int n = n0 + trow*4 + i;
        #pragma unroll
        for(int j=0;j<2;j++)
            g_cpre[(tb*Nc + n)*32 + tcol*2 + j] = acc[i][j];
    }
}

// ---------------- step 0: h = (1-u)*tanh(cpre), u = sigmoid(gpre_u) ----------------
__global__ void k_step0(){
    int idx = blockIdx.x*blockDim.x + threadIdx.x;   // over Nc*BDc
    int n = idx>>7, j = idx&127, b = j>>5, d = j&31;
    float u = 1.f/(1.f + expf(-g_gpre[(b*Nc + n)*64 + 32 + d]));
    float c = tanhf(g_cpre[(b*Nc + n)*32 + d]);
    g_h[idx] = (1.f - u)*c;
}

// ---------------- gate GEMM + sigmoid + r*h / u ----------------
__global__ __launch_bounds__(256) void k_gate(int t){
    int n0 = blockIdx.x*16;      // 16 n -> 64 (n,b) rows
    __shared__ float Ws[128*64];
    __shared__ float As[32*65];
    int tid = threadIdx.x;
    for(int i=tid;i<128*64;i+=256) Ws[i] = g_Wgh[i];
    int trow = tid>>4, tcol = tid&15;       // rows: n_l=trow, b=i ; cols: tcol*4+j
    float acc[4][4];
    int n = n0 + trow;
    #pragma unroll
    for(int i=0;i<4;i++)
        #pragma unroll
        for(int j=0;j<4;j++)
            acc[i][j] = g_gpre[((t*Bc + i)*Nc + n)*64 + tcol*4 + j];
    #pragma unroll
    for(int seg=0; seg<4; seg++){
        const float* __restrict__ sa = (seg==0)?g_h:(seg==1)?g_y1:(seg==2)?g_y2:g_y3;
        __syncthreads();
        for(int i2=tid; i2<2048; i2+=256){
            int nl = i2>>7, j = i2&127;
            As[(j&31)*65 + nl*4 + (j>>5)] = sa[(n0+nl)*BDc + j];
        }
        __syncthreads();
        #pragma unroll
        for(int k=0;k<32;k++){
            float a0 = As[k*65 + trow*4 + 0];
            float a1 = As[k*65 + trow*4 + 1];
            float a2 = As[k*65 + trow*4 + 2];
            float a3 = As[k*65 + trow*4 + 3];
            float4 bv = *(const float4*)&Ws[(seg*32+k)*64 + tcol*4];
            acc[0][0]=fmaf(a0,bv.x,acc[0][0]); acc[0][1]=fmaf(a0,bv.y,acc[0][1]);
            acc[0][2]=fmaf(a0,bv.z,acc[0][2]); acc[0][3]=fmaf(a0,bv.w,acc[0][3]);
            acc[1][0]=fmaf(a1,bv.x,acc[1][0]); acc[1][1]=fmaf(a1,bv.y,acc[1][1]);
            acc[1][2]=fmaf(a1,bv.z,acc[1][2]); acc[1][3]=fmaf(a1,bv.w,acc[1][3]);
            acc[2][0]=fmaf(a2,bv.x,acc[2][0]); acc[2][1]=fmaf(a2,bv.y,acc[2][1]);
            acc[2][2]=fmaf(a2,bv.z,acc[2][2]); acc[2][3]=fmaf(a2,bv.w,acc[2][3]);
            acc[3][0]=fmaf(a3,bv.x,acc[3][0]); acc[3][1]=fmaf(a3,bv.y,acc[3][1]);
            acc[3][2]=fmaf(a3,bv.z,acc[3][2]); acc[3][3]=fmaf(a3,bv.w,acc[3][3]);
        }
    }
    #pragma unroll
    for(int i=0;i<4;i++){
        #pragma unroll
        for(int j=0;j<4;j++){
            int o = tcol*4 + j;
            float v = 1.f/(1.f + expf(-acc[i][j]));
            int addr = n*BDc + i*32 + (o&31);
            if(o < 32) g_rh[addr] = v * g_h[addr];
            else       g_u[addr]  = v;
        }
    }
}

// ---------------- cand GEMM + tanh + GRU update ----------------
__global__ __launch_bounds__(256) void k_cand(int t){
    int n0 = blockIdx.x*16;
    __shared__ float Ws[128*32];
    __shared__ float As[32*65];
    int tid = threadIdx.x;
    for(int i=tid;i<128*32;i+=256) Ws[i] = g_Wch[i];
    int trow = tid>>4, tcol = tid&15;       // rows: n_l=trow, b=i ; cols: tcol*2+j
    float acc[4][2];
    int n = n0 + trow;
    #pragma unroll
    for(int i=0;i<4;i++)
        #pragma unroll
        for(int j=0;j<2;j++)
            acc[i][j] = g_cpre[((t*Bc + i)*Nc + n)*32 + tcol*2 + j];
    #pragma unroll
    for(int seg=0; seg<4; seg++){
        const float* __restrict__ sa = (seg==0)?g_rh:(seg==1)?g_y1:(seg==2)?g_y2:g_y3;
        __syncthreads();
        for(int i2=tid; i2<2048; i2+=256){
            int nl = i2>>7, j = i2&127;
            As[(j&31)*65 + nl*4 + (j>>5)] = sa[(n0+nl)*BDc + j];
        }
        __syncthreads();
        #pragma unroll
        for(int k=0;k<32;k++){
            float a0 = As[k*65 + trow*4 + 0];
            float a1 = As[k*65 + trow*4 + 1];
            float a2 = As[k*65 + trow*4 + 2];
            float a3 = As[k*65 + trow*4 + 3];
            float b0 = Ws[(seg*32+k)*32 + tcol*2 + 0];
            float b1 = Ws[(seg*32+k)*32 + tcol*2 + 1];
            acc[0][0]=fmaf(a0,b0,acc[0][0]); acc[0][1]=fmaf(a0,b1,acc[0][1]);
            acc[1][0]=fmaf(a1,b0,acc[1][0]); acc[1][1]=fmaf(a1,b1,acc[1][1]);
            acc[2][0]=fmaf(a2,b0,acc[2][0]); acc[2][1]=fmaf(a2,b1,acc[2][1]);
            acc[3][0]=fmaf(a3,b0,acc[3][0]); acc[3][1]=fmaf(a3,b1,acc[3][1]);
        }
    }
    #pragma unroll
    for(int i=0;i<4;i++){
        #pragma unroll
        for(int j=0;j<2;j++){
            int o = tcol*2 + j;
            int addr = n*BDc + i*32 + o;
            float c = tanhf(acc[i][j]);
            float u = g_u[addr];
            float h = g_h[addr];
            g_h[addr] = u*h + (1.f - u)*c;
        }
    }
}

// ---------------- output head ----------------
__global__ void k_out(const float* __restrict__ W1, const float* __restrict__ b1,
                      const float* __restrict__ W2, const float* __restrict__ b2,
                      float* __restrict__ out){
    int r = blockIdx.x*8 + (threadIdx.x>>5);      // r = b*N + n
    int lane = threadIdx.x & 31;
    int b = r>>11, n = r&2047;
    float hv = g_h[n*BDc + b*Dc + lane];
    float hid = b1[lane];
    #pragma unroll
    for(int j=0;j<32;j++) hid = fmaf(__shfl_sync(0xffffffffu, hv, j), W1[j*32+lane], hid);
    hid = fmaxf(hid, 0.f);
    float o = (lane < Qc) ? b2[lane] : 0.f;
    #pragma unroll
    for(int d=0;d<32;d++){
        float s = __shfl_sync(0xffffffffu, hid, d);
        if(lane < Qc) o = fmaf(s, W2[d*Qc + lane], o);
    }
    if(lane < Qc) out[(b*Qc + lane)*Nc + n] = o;
}

// ---------------- launcher ----------------
extern "C" void kernel_launch(void* const* d_in, const int* in_sizes, int n_in,
                              void* d_out, int out_size){
    const float* X     = (const float*)d_in[0];
    const int*   TE    = (const int*)  d_in[1];
    const float* L     = (const float*)d_in[2];
    const float* SE    = (const float*)d_in[3];
    const float* W_se1 = (const float*)d_in[4];  const float* b_se1 = (const float*)d_in[5];
    const float* W_se2 = (const float*)d_in[6];  const float* b_se2 = (const float*)d_in[7];
    const float* W_te1 = (const float*)d_in[8];  const float* b_te1 = (const float*)d_in[9];
    const float* W_te2 = (const float*)d_in[10]; const float* b_te2 = (const float*)d_in[11];
    const float* W_in1 = (const float*)d_in[12]; const float* b_in1 = (const float*)d_in[13];
    const float* W_in2 = (const float*)d_in[14]; const float* b_in2 = (const float*)d_in[15];
    const float* W_gate= (const float*)d_in[16];
    const float* b_gate= (const float*)d_in[17];
    const float* W_cand= (const float*)d_in[18];
    const float* b_cand= (const float*)d_in[19];
    const float* W_out1= (const float*)d_in[20]; const float* b_out1= (const float*)d_in[21];
    const float* W_out2= (const float*)d_in[22]; const float* b_out2= (const float*)d_in[23];
    float* out = (float*)d_out;

    k_ell<<<Nc/8, 256>>>(L);
    k_pack<<<32, 256>>>(W_gate, W_cand);
    k_se<<<Nc/8, 256>>>(SE, W_se1, b_se1, W_se2, b_se2);
    k_te<<<Bc*(Pc+Qc), 32>>>(TE, W_te1, b_te1, W_te2, b_te2);
    k_xembed<<<(Pc*Bc*Nc)/8, 256>>>(X, W_in1, b_in1, W_in2, b_in2);

    // Chebyshev polys of x for all timesteps (1536 columns)
    k_spmm<<<Nc, 256>>>(0, -1, 1, PBDc, 1.f);   // X1 = L X0
    k_spmm<<<Nc, 256>>>(1,  0, 2, PBDc, 2.f);   // X2 = 2 L X1 - X0
    k_spmm<<<Nc, 256>>>(2,  1, 3, PBDc, 2.f);   // X3 = 2 L X2 - X1

    dim3 pg(32, Pc*Bc);
    k_pre_gate<<<pg, 256>>>(b_gate);
    k_pre_cand<<<pg, 256>>>(b_cand);

    k_step0<<<512, 512>>>();

    for(int t=1; t<Pc; t++){
        k_spmm<<<Nc, 128>>>(4, -1, 5, BDc, 1.f);   // y1 = L h
        k_spmm<<<Nc, 128>>>(5,  4, 6, BDc, 2.f);   // y2 = 2 L y1 - h
        k_spmm<<<Nc, 128>>>(6,  5, 7, BDc, 2.f);   // y3 = 2 L y2 - y1
        k_gate<<<128, 256>>>(t);
        k_spmm<<<Nc, 128>>>(8, -1, 5, BDc, 1.f);   // z1 = L rh
        k_spmm<<<Nc, 128>>>(5,  8, 6, BDc, 2.f);
        k_spmm<<<Nc, 128>>>(6,  5, 7, BDc, 2.f);
        k_cand<<<128, 256>>>(t);
    }

    k_out<<<(Bc*Nc)/8, 256>>>(W_out1, b_out1, W_out2, b_out2, out);
}